// round 4
// baseline (speedup 1.0000x reference)
#include <cuda_runtime.h>
#include <cuda_bf16.h>
#include <math.h>
#include <stdint.h>

// ---------------- problem constants ----------------
#define HEADS   24
#define HDIM    128
#define DIM     3072
#define S_TXT   512
#define S_IMG   2048
#define S_TOT   2560
#define EPS     1e-5f
#define QK_SCALE 0.08838834764831845f

#define KCAT        9216            // 3*DIM
#define HCAT        384             // 3*HDIM
#define PCAT_W      7680            // 3*S_TOT
#define APITCH      72              // A/B-NT smem pitch (bf16) for 64-wide chunks
#define BPITCH_T    136             // B-NN ([k][n]) smem pitch
#define STAGE_ELEMS (2 * 128 * APITCH)      // 18432 elems
#define STAGE_BYTES (STAGE_ELEMS * 2)       // 36864
#define SMEM_BYTES  (3 * STAGE_BYTES)       // 110592

// ---------------- scratch ----------------
__device__ float          g_qkv[(size_t)3 * S_TOT * DIM];
__device__ float          g_of[(size_t)S_TOT * DIM];
__device__ float          g_sc[(size_t)HEADS * S_TOT * S_TOT];
__device__ __nv_bfloat16  g_xcat[(size_t)S_IMG * KCAT];
__device__ __nv_bfloat16  g_ecat[(size_t)S_TXT * KCAT];
__device__ __nv_bfloat16  g_qcat[(size_t)S_TOT * KCAT];
__device__ __nv_bfloat16  g_kcat[(size_t)S_TOT * KCAT];
__device__ __nv_bfloat16  g_vcat[(size_t)PCAT_W * DIM];
__device__ __nv_bfloat16  g_ocat[(size_t)S_TOT * KCAT];
__device__ __nv_bfloat16  g_pcat[(size_t)HEADS * S_TOT * PCAT_W];
__device__ __nv_bfloat16  g_wcat[8][(size_t)DIM * KCAT];   // wq wk wv waq wak wav wo wao

// ---------------- helpers ----------------
struct bf16x4 { __nv_bfloat162 a, b; };

__device__ __forceinline__ void split4(float4 v, bf16x4& hi, bf16x4& lo) {
    __nv_bfloat162 h01 = __floats2bfloat162_rn(v.x, v.y);
    __nv_bfloat162 h23 = __floats2bfloat162_rn(v.z, v.w);
    float2 f01 = __bfloat1622float2(h01);
    float2 f23 = __bfloat1622float2(h23);
    hi.a = h01; hi.b = h23;
    lo.a = __floats2bfloat162_rn(v.x - f01.x, v.y - f01.y);
    lo.b = __floats2bfloat162_rn(v.z - f23.x, v.w - f23.y);
}

__device__ __forceinline__ uint32_t smem_u32(const void* p) {
    return static_cast<uint32_t>(__cvta_generic_to_shared(p));
}
__device__ __forceinline__ void cp16(void* dst, const void* src) {
    asm volatile("cp.async.cg.shared.global [%0], [%1], 16;"
                 :: "r"(smem_u32(dst)), "l"(src));
}
__device__ __forceinline__ void cp_commit() {
    asm volatile("cp.async.commit_group;");
}
template<int N>
__device__ __forceinline__ void cp_wait() {
    asm volatile("cp.async.wait_group %0;" :: "n"(N));
}
__device__ __forceinline__ void ldm_x4(uint32_t a, uint32_t& r0, uint32_t& r1,
                                       uint32_t& r2, uint32_t& r3) {
    asm volatile("ldmatrix.sync.aligned.m8n8.x4.shared.b16 {%0,%1,%2,%3}, [%4];"
                 : "=r"(r0), "=r"(r1), "=r"(r2), "=r"(r3) : "r"(a));
}
__device__ __forceinline__ void ldm_x4t(uint32_t a, uint32_t& r0, uint32_t& r1,
                                        uint32_t& r2, uint32_t& r3) {
    asm volatile("ldmatrix.sync.aligned.m8n8.x4.trans.shared.b16 {%0,%1,%2,%3}, [%4];"
                 : "=r"(r0), "=r"(r1), "=r"(r2), "=r"(r3) : "r"(a));
}
__device__ __forceinline__ void mma16816(float& c0, float& c1, float& c2, float& c3,
                                         uint32_t a0, uint32_t a1, uint32_t a2, uint32_t a3,
                                         uint32_t b0, uint32_t b1) {
    asm volatile("mma.sync.aligned.m16n8k16.row.col.f32.bf16.bf16.f32 "
                 "{%0,%1,%2,%3}, {%4,%5,%6,%7}, {%8,%9}, {%0,%1,%2,%3};"
                 : "+f"(c0), "+f"(c1), "+f"(c2), "+f"(c3)
                 : "r"(a0), "r"(a1), "r"(a2), "r"(a3), "r"(b0), "r"(b1));
}

// ---------------- bf16 GEMM body, 128x128 CTA, 3-stage cp.async ----------------
// TRANS_B=false: B row-major [N,K] (NT). TRANS_B=true: B row-major [K,N] (NN).
// K%64==0, M%128, N%128, 16B-aligned bases & strides.
template<bool TRANS_B>
__device__ __forceinline__ void gemm_body(
    const __nv_bfloat16* __restrict__ A, const __nv_bfloat16* __restrict__ B,
    const float* __restrict__ bias, float* __restrict__ C,
    int K, int lda, int ldb, int ldc, float scale)
{
    extern __shared__ __nv_bfloat16 sm[];

    const int row0 = blockIdx.y * 128;
    const int col0 = blockIdx.x * 128;
    const int tid  = threadIdx.x;
    const int lane = tid & 31;
    const int warp = tid >> 5;
    const int wm   = warp & 3;
    const int wn   = warp >> 2;

    const int a_row  = tid >> 1;
    const int a_col0 = (tid & 1) * 32;
    const int b_row  = tid >> 2;          // NN: k row
    const int b_col0 = (tid & 3) * 32;    // NN: n col

    auto load_stage = [&](int c, int stage) {
        __nv_bfloat16* As = sm + stage * STAGE_ELEMS;
        __nv_bfloat16* Bs = As + 128 * APITCH;
        const __nv_bfloat16* Ag = A + (size_t)(row0 + a_row) * lda + c * 64 + a_col0;
        __nv_bfloat16* Ad = As + a_row * APITCH + a_col0;
#pragma unroll
        for (int i = 0; i < 4; i++) cp16(Ad + i * 8, Ag + i * 8);
        if (!TRANS_B) {
            const __nv_bfloat16* Bg = B + (size_t)(col0 + a_row) * ldb + c * 64 + a_col0;
            __nv_bfloat16* Bd = Bs + a_row * APITCH + a_col0;
#pragma unroll
            for (int i = 0; i < 4; i++) cp16(Bd + i * 8, Bg + i * 8);
        } else {
            const __nv_bfloat16* Bg = B + (size_t)(c * 64 + b_row) * ldb + col0 + b_col0;
            __nv_bfloat16* Bd = Bs + b_row * BPITCH_T + b_col0;
#pragma unroll
            for (int i = 0; i < 4; i++) cp16(Bd + i * 8, Bg + i * 8);
        }
        cp_commit();
    };

    // ldmatrix lane maps
    const int m_off = (lane & 7) + ((lane >> 3) & 1) * 8;
    const int k_off = (lane >> 4) * 8;
    const int n_off = (lane & 7) + (lane >> 4) * 8;
    const int kb_off = ((lane >> 3) & 1) * 8;

    uint32_t aBase[2], bBase[4];
#pragma unroll
    for (int mi = 0; mi < 2; mi++)
        aBase[mi] = smem_u32(sm + (wm * 32 + mi * 16 + m_off) * APITCH + k_off);
    if (!TRANS_B) {
#pragma unroll
        for (int np = 0; np < 4; np++)
            bBase[np] = smem_u32(sm + 128 * APITCH +
                                 (wn * 64 + np * 16 + n_off) * APITCH + kb_off);
    } else {
        const int t_krow = (lane & 7) + ((lane >> 3) & 1) * 8;
        const int t_noff = (lane >> 4) * 8;
#pragma unroll
        for (int np = 0; np < 4; np++)
            bBase[np] = smem_u32(sm + 128 * APITCH +
                                 t_krow * BPITCH_T + wn * 64 + np * 16 + t_noff);
    }

    float acc[2][8][4];
#pragma unroll
    for (int i = 0; i < 2; i++)
#pragma unroll
        for (int j = 0; j < 8; j++)
#pragma unroll
            for (int c = 0; c < 4; c++) acc[i][j][c] = 0.f;

    const int nc = K / 64;
    load_stage(0, 0);
    load_stage(1, 1);

    int stage = 0;
    for (int c = 0; c < nc; c++) {
        cp_wait<1>();
        __syncthreads();
        if (c + 2 < nc) load_stage(c + 2, (c + 2) % 3);
        else            cp_commit();                       // empty group keeps count

        const uint32_t so = (uint32_t)stage * STAGE_BYTES;
#pragma unroll
        for (int ks = 0; ks < 4; ks++) {
            uint32_t Ar[2][4], Br[8][2];
#pragma unroll
            for (int mi = 0; mi < 2; mi++)
                ldm_x4(aBase[mi] + so + ks * 32, Ar[mi][0], Ar[mi][1], Ar[mi][2], Ar[mi][3]);
            if (!TRANS_B) {
#pragma unroll
                for (int np = 0; np < 4; np++)
                    ldm_x4(bBase[np] + so + ks * 32, Br[2 * np][0], Br[2 * np][1],
                           Br[2 * np + 1][0], Br[2 * np + 1][1]);
            } else {
#pragma unroll
                for (int np = 0; np < 4; np++)
                    ldm_x4t(bBase[np] + so + ks * (16 * BPITCH_T * 2),
                            Br[2 * np][0], Br[2 * np][1],
                            Br[2 * np + 1][0], Br[2 * np + 1][1]);
            }
#pragma unroll
            for (int mi = 0; mi < 2; mi++)
#pragma unroll
                for (int nj = 0; nj < 8; nj++)
                    mma16816(acc[mi][nj][0], acc[mi][nj][1], acc[mi][nj][2], acc[mi][nj][3],
                             Ar[mi][0], Ar[mi][1], Ar[mi][2], Ar[mi][3],
                             Br[nj][0], Br[nj][1]);
        }
        stage = (stage + 1 == 3) ? 0 : stage + 1;
    }

#pragma unroll
    for (int mi = 0; mi < 2; mi++) {
#pragma unroll
        for (int nj = 0; nj < 8; nj++) {
            const int row = row0 + wm * 32 + mi * 16 + (lane >> 2);
            const int col = col0 + wn * 64 + nj * 8 + (lane & 3) * 2;
            float b0 = bias ? bias[col]     : 0.f;
            float b1 = bias ? bias[col + 1] : 0.f;
            float2 v0 = { acc[mi][nj][0] * scale + b0, acc[mi][nj][1] * scale + b1 };
            float2 v1 = { acc[mi][nj][2] * scale + b0, acc[mi][nj][3] * scale + b1 };
            *reinterpret_cast<float2*>(&C[(size_t)row * ldc + col])       = v0;
            *reinterpret_cast<float2*>(&C[(size_t)(row + 8) * ldc + col]) = v1;
        }
    }
}

template<bool TRANS_B>
__global__ void __launch_bounds__(256)
gemm_cat_k(const __nv_bfloat16* __restrict__ A, const __nv_bfloat16* __restrict__ B,
           const float* __restrict__ bias, float* __restrict__ C,
           int K, int lda, int ldb, int ldc,
           long long sA, long long sB, long long sC, float scale)
{
    gemm_body<TRANS_B>(A + (size_t)blockIdx.z * sA, B + (size_t)blockIdx.z * sB,
                       bias, C + (size_t)blockIdx.z * sC, K, lda, ldb, ldc, scale);
}

struct QKV3 {
    const __nv_bfloat16 *B0, *B1, *B2;
    float *C0, *C1, *C2;
    const float *b0, *b1, *b2;
};

__global__ void __launch_bounds__(256)
qkv3_k(const __nv_bfloat16* __restrict__ A, QKV3 p, int K, int lda, int ldb, int ldc)
{
    const __nv_bfloat16* B; float* C; const float* bias;
    if (blockIdx.z == 0)      { B = p.B0; C = p.C0; bias = p.b0; }
    else if (blockIdx.z == 1) { B = p.B1; C = p.C1; bias = p.b1; }
    else                      { B = p.B2; C = p.C2; bias = p.b2; }
    gemm_body<false>(A, B, bias, C, K, lda, ldb, ldc, 1.f);
}

// ---------------- converts ----------------
// fp32 [M, DIM] -> cat bf16 [M, KCAT]; PAT 0: hi|hi|lo (A side), 1: hi|lo|hi (B side)
template<int PAT>
__global__ void __launch_bounds__(256)
conv_cat_k(const float* __restrict__ in, __nv_bfloat16* __restrict__ out, int M)
{
    const int idx = blockIdx.x * 256 + threadIdx.x;      // one float4
    const int tot = M * (DIM / 4);
    if (idx >= tot) return;
    const int m = idx / (DIM / 4);
    const int c = (idx % (DIM / 4)) * 4;
    float4 v = *reinterpret_cast<const float4*>(in + (size_t)m * DIM + c);
    bf16x4 hi, lo;
    split4(v, hi, lo);
    __nv_bfloat16* base = out + (size_t)m * KCAT + c;
    *reinterpret_cast<bf16x4*>(base)            = hi;
    *reinterpret_cast<bf16x4*>(base + DIM)      = PAT ? lo : hi;
    *reinterpret_cast<bf16x4*>(base + 2 * DIM)  = PAT ? hi : lo;
}

// fp32 v [S_TOT, DIM] -> vcat [3*S_TOT, DIM]: rows hi | lo | hi
__global__ void __launch_bounds__(256)
conv_v_k(const float* __restrict__ in, __nv_bfloat16* __restrict__ out)
{
    const int idx = blockIdx.x * 256 + threadIdx.x;
    const int tot = S_TOT * (DIM / 4);
    if (idx >= tot) return;
    const int s = idx / (DIM / 4);
    const int c = (idx % (DIM / 4)) * 4;
    float4 v = *reinterpret_cast<const float4*>(in + (size_t)s * DIM + c);
    bf16x4 hi, lo;
    split4(v, hi, lo);
    *reinterpret_cast<bf16x4*>(out + (size_t)s * DIM + c)                 = hi;
    *reinterpret_cast<bf16x4*>(out + (size_t)(S_TOT + s) * DIM + c)       = lo;
    *reinterpret_cast<bf16x4*>(out + (size_t)(2 * S_TOT + s) * DIM + c)   = hi;
}

// ---------------- RMSNorm + RoPE -> cat bf16 [s][h][384] ----------------
// PAT 0 (q): hi|hi|lo ; PAT 1 (k): hi|lo|hi
template<int PAT>
__global__ void __launch_bounds__(128)
rmsnorm_rope_cat_k(const float* __restrict__ buf, __nv_bfloat16* __restrict__ outc,
                   const float* __restrict__ w_enc, const float* __restrict__ w_img,
                   const float* __restrict__ rcos,  const float* __restrict__ rsin)
{
    const int wrp  = blockIdx.x * 4 + (threadIdx.x >> 5);
    const int lane = threadIdx.x & 31;
    const int s = wrp / HEADS;
    const int h = wrp % HEADS;

    const float* w = (s < S_TXT) ? w_enc : w_img;
    const float* row = buf + (size_t)s * DIM + h * HDIM;

    float4 x = *reinterpret_cast<const float4*>(row + lane * 4);
    float ss = x.x * x.x + x.y * x.y + x.z * x.z + x.w * x.w;
#pragma unroll
    for (int o = 16; o; o >>= 1) ss += __shfl_xor_sync(0xffffffffu, ss, o);
    float inv = rsqrtf(ss * (1.f / HDIM) + EPS);

    float4 wv = *reinterpret_cast<const float4*>(w + lane * 4);
    float y0 = x.x * inv * wv.x, y1 = x.y * inv * wv.y;
    float y2 = x.z * inv * wv.z, y3 = x.w * inv * wv.w;

    const float4 c  = *reinterpret_cast<const float4*>(rcos + (size_t)s * HDIM + lane * 4);
    const float4 sn = *reinterpret_cast<const float4*>(rsin + (size_t)s * HDIM + lane * 4);
    float4 o;
    o.x = y0 * c.x - y1 * sn.x;
    o.y = y1 * c.y + y0 * sn.y;
    o.z = y2 * c.z - y3 * sn.z;
    o.w = y3 * c.w + y2 * sn.w;

    bf16x4 hi, lo;
    split4(o, hi, lo);
    __nv_bfloat16* base = outc + (size_t)s * KCAT + h * HCAT + lane * 4;
    *reinterpret_cast<bf16x4*>(base)             = hi;
    *reinterpret_cast<bf16x4*>(base + HDIM)      = PAT ? lo : hi;
    *reinterpret_cast<bf16x4*>(base + 2 * HDIM)  = PAT ? hi : lo;
}

// ---------------- softmax -> Pcat bf16 [hi|hi|lo] ----------------
__global__ void __launch_bounds__(256)
softmax_cat_k(const float* __restrict__ scores, __nv_bfloat16* __restrict__ pcat)
{
    const size_t r = blockIdx.x;
    const float* row = scores + r * S_TOT;
    __nv_bfloat16* prow = pcat + r * PCAT_W;
    const int tid = threadIdx.x;
    __shared__ float red[8];

    float m = -1e30f;
    for (int i = tid; i < S_TOT; i += 256) m = fmaxf(m, row[i]);
#pragma unroll
    for (int o = 16; o; o >>= 1) m = fmaxf(m, __shfl_xor_sync(0xffffffffu, m, o));
    if ((tid & 31) == 0) red[tid >> 5] = m;
    __syncthreads();
    m = red[0];
#pragma unroll
    for (int i = 1; i < 8; i++) m = fmaxf(m, red[i]);
    __syncthreads();

    float sum = 0.f;
    float e[10];
#pragma unroll
    for (int j = 0; j < 10; j++) {
        e[j] = __expf(row[tid + j * 256] - m);
        sum += e[j];
    }
#pragma unroll
    for (int o = 16; o; o >>= 1) sum += __shfl_xor_sync(0xffffffffu, sum, o);
    if ((tid & 31) == 0) red[tid >> 5] = sum;
    __syncthreads();
    sum = 0.f;
#pragma unroll
    for (int i = 0; i < 8; i++) sum += red[i];
    const float inv = 1.f / sum;

#pragma unroll
    for (int j = 0; j < 10; j++) {
        const int i = tid + j * 256;
        float p = e[j] * inv;
        __nv_bfloat16 hb = __float2bfloat16_rn(p);
        __nv_bfloat16 lb = __float2bfloat16_rn(p - __bfloat162float(hb));
        prow[i]             = hb;
        prow[S_TOT + i]     = hb;
        prow[2 * S_TOT + i] = lb;
    }
}

// ---------------- launch ----------------
extern "C" void kernel_launch(void* const* d_in, const int* in_sizes, int n_in,
                              void* d_out, int out_size)
{
    (void)in_sizes; (void)n_in; (void)out_size;
    const float* x    = (const float*)d_in[0];
    const float* ehs  = (const float*)d_in[1];
    const float* rcos = (const float*)d_in[2];
    const float* rsin = (const float*)d_in[3];
    const float* W[8] = { (const float*)d_in[4],  (const float*)d_in[5],
                          (const float*)d_in[6],  (const float*)d_in[7],
                          (const float*)d_in[8],  (const float*)d_in[9],
                          (const float*)d_in[17], (const float*)d_in[19] };
    const float* baq  = (const float*)d_in[10];
    const float* bak  = (const float*)d_in[11];
    const float* bav  = (const float*)d_in[12];
    const float* nqw  = (const float*)d_in[13];
    const float* nkw  = (const float*)d_in[14];
    const float* naqw = (const float*)d_in[15];
    const float* nakw = (const float*)d_in[16];
    const float* bo   = (const float*)d_in[18];
    const float* bao  = (const float*)d_in[20];
    float* out = (float*)d_out;

    float *qkv, *of, *sc;
    __nv_bfloat16 *xcat, *ecat, *qcat, *kcat, *vcat, *ocat, *pcat, *wcat;
    cudaGetSymbolAddress((void**)&qkv,  g_qkv);
    cudaGetSymbolAddress((void**)&of,   g_of);
    cudaGetSymbolAddress((void**)&sc,   g_sc);
    cudaGetSymbolAddress((void**)&xcat, g_xcat);
    cudaGetSymbolAddress((void**)&ecat, g_ecat);
    cudaGetSymbolAddress((void**)&qcat, g_qcat);
    cudaGetSymbolAddress((void**)&kcat, g_kcat);
    cudaGetSymbolAddress((void**)&vcat, g_vcat);
    cudaGetSymbolAddress((void**)&ocat, g_ocat);
    cudaGetSymbolAddress((void**)&pcat, g_pcat);
    cudaGetSymbolAddress((void**)&wcat, g_wcat);

    cudaFuncSetAttribute(gemm_cat_k<false>, cudaFuncAttributeMaxDynamicSharedMemorySize, SMEM_BYTES);
    cudaFuncSetAttribute(gemm_cat_k<true>,  cudaFuncAttributeMaxDynamicSharedMemorySize, SMEM_BYTES);
    cudaFuncSetAttribute(qkv3_k,            cudaFuncAttributeMaxDynamicSharedMemorySize, SMEM_BYTES);

    const dim3 blk(256);
    const size_t WSTRIDE = (size_t)DIM * KCAT;
    float *q = qkv, *k = qkv + (size_t)S_TOT * DIM, *v = qkv + (size_t)2 * S_TOT * DIM;

    // ---- converts: activations + 8 weights
    conv_cat_k<0><<<dim3((S_IMG * DIM / 4 + 255) / 256), blk>>>(x,   xcat, S_IMG);
    conv_cat_k<0><<<dim3((S_TXT * DIM / 4 + 255) / 256), blk>>>(ehs, ecat, S_TXT);
    for (int i = 0; i < 8; i++)
        conv_cat_k<1><<<dim3((DIM * DIM / 4 + 255) / 256), blk>>>(W[i], wcat + i * WSTRIDE, DIM);

    // ---- QKV projections (z batches the 3 weights)
    {
        QKV3 pi = { wcat + 0 * WSTRIDE, wcat + 1 * WSTRIDE, wcat + 2 * WSTRIDE,
                    q + (size_t)S_TXT * DIM, k + (size_t)S_TXT * DIM, v + (size_t)S_TXT * DIM,
                    nullptr, nullptr, nullptr };
        qkv3_k<<<dim3(DIM / 128, S_IMG / 128, 3), blk, SMEM_BYTES>>>(xcat, pi, KCAT, KCAT, KCAT, DIM);
        QKV3 pe = { wcat + 3 * WSTRIDE, wcat + 4 * WSTRIDE, wcat + 5 * WSTRIDE,
                    q, k, v, baq, bak, bav };
        qkv3_k<<<dim3(DIM / 128, S_TXT / 128, 3), blk, SMEM_BYTES>>>(ecat, pe, KCAT, KCAT, KCAT, DIM);
    }

    // ---- RMSNorm+RoPE -> qcat/kcat; v -> vcat
    {
        dim3 g((S_TOT * HEADS) / 4);
        rmsnorm_rope_cat_k<0><<<g, dim3(128)>>>(q, qcat, naqw, nqw, rcos, rsin);
        rmsnorm_rope_cat_k<1><<<g, dim3(128)>>>(k, kcat, nakw, nkw, rcos, rsin);
        conv_v_k<<<dim3((S_TOT * DIM / 4 + 255) / 256), blk>>>(v, vcat);
    }

    // ---- scores = scale * qcat · kcatᵀ  (per head, K'=384)
    gemm_cat_k<false><<<dim3(S_TOT / 128, S_TOT / 128, HEADS), blk, SMEM_BYTES>>>(
        qcat, kcat, nullptr, sc, HCAT, KCAT, KCAT, S_TOT,
        HCAT, HCAT, (long long)S_TOT * S_TOT, QK_SCALE);

    // ---- softmax -> pcat
    softmax_cat_k<<<dim3(HEADS * S_TOT), blk>>>(sc, pcat);

    // ---- O = Pcat · Vcat  (NN, per head; K'=7680)
    gemm_cat_k<true><<<dim3(1, S_TOT / 128, HEADS), blk, SMEM_BYTES>>>(
        pcat, vcat, nullptr, of, PCAT_W, PCAT_W, DIM, DIM,
        (long long)S_TOT * PCAT_W, HDIM, HDIM, 1.f);

    // ---- o -> ocat; output projections
    conv_cat_k<0><<<dim3((S_TOT * DIM / 4 + 255) / 256), blk>>>(of, ocat, S_TOT);

    gemm_cat_k<false><<<dim3(DIM / 128, S_IMG / 128, 1), blk, SMEM_BYTES>>>(
        ocat + (size_t)S_TXT * KCAT, wcat + 6 * WSTRIDE, bo, out,
        KCAT, KCAT, KCAT, DIM, 0, 0, 0, 1.f);
    gemm_cat_k<false><<<dim3(DIM / 128, S_TXT / 128, 1), blk, SMEM_BYTES>>>(
        ocat, wcat + 7 * WSTRIDE, bao, out + (size_t)S_IMG * DIM,
        KCAT, KCAT, KCAT, DIM, 0, 0, 0, 1.f);
}